// round 1
// baseline (speedup 1.0000x reference)
#include <cuda_runtime.h>

#define EPSF 1e-5f

// Scratch (allocation-free rule: __device__ globals)
__device__ float g_xn[2 * 128 * 256];   // normalized+relu'd x, (b, c, hw)
__device__ float g_yn[2 * 128 * 256];   // normalized+relu'd y, (b, d, hw)
__device__ float g_s [2 * 128 * 256];   // s[b, o, i]

__device__ __forceinline__ float warp_sum(float v) {
#pragma unroll
    for (int o = 16; o > 0; o >>= 1) v += __shfl_down_sync(0xffffffffu, v, o);
    return v;
}

// ---------------------------------------------------------------------------
// Kernel 1: instance norm + relu for x (with pos_emb add) and y.
// grid = 512 blocks (first 256 -> x rows, next 256 -> y rows), 256 threads.
// Each block handles one (b, channel) row of 256 spatial elements.
// ---------------------------------------------------------------------------
__global__ void k_norm(const float* __restrict__ x, const float* __restrict__ y,
                       const float* __restrict__ pos) {
    __shared__ float sh[16];
    const int bid  = blockIdx.x;
    const int i    = threadIdx.x;          // spatial index 0..255
    const bool isx = bid < 256;
    const int idx  = bid & 255;            // b*128 + channel
    const int c    = idx & 127;

    float v = (isx ? x : y)[idx * 256 + i];
    if (isx) v += pos[i * 128 + c];        // pos[c,h,w] = pos_emb[i, c]

    float s1 = warp_sum(v);
    float s2 = warp_sum(v * v);
    const int lane = i & 31, wid = i >> 5;
    if (lane == 0) { sh[wid] = s1; sh[8 + wid] = s2; }
    __syncthreads();
    float t1 = 0.f, t2 = 0.f;
#pragma unroll
    for (int w = 0; w < 8; w++) { t1 += sh[w]; t2 += sh[8 + w]; }

    const float m   = t1 * (1.f / 256.f);
    const float var = t2 * (1.f / 256.f) - m * m;
    const float r   = rsqrtf(var + EPSF);
    const float o   = fmaxf((v - m) * r, 0.f);
    (isx ? g_xn : g_yn)[idx * 256 + i] = o;
}

// ---------------------------------------------------------------------------
// Kernel 2: fused A/B GEMVs + separable instance-norm of z + relu + sum over j.
//   A[j] = sum_c Wi[o,c]*xn[b,c,j]
//   B[j] = sum_c Wj[o,c]*xn[b,c,j] + sum_d Wy[o,d]*yn[b,d,j]
//   z[i,j] = A[j] + B[i] + b1[o]; inorm over (i,j) is separable:
//     mean = Ā+B̄+b1 (b1 cancels), var = varA + varB
//   s[i] = sum_j relu(a'_j + b'_i)
// grid = 256 blocks (b*128+o), 256 threads (j / i).
// ---------------------------------------------------------------------------
__global__ void k_relate(const float* __restrict__ w1) {
    __shared__ float ws[384];
    __shared__ float red[32];
    __shared__ float as[256];

    const int bid = blockIdx.x;
    const int b   = bid >> 7;
    const int o   = bid & 127;
    const int j   = threadIdx.x;

    for (int t = j; t < 384; t += 256) ws[t] = w1[o * 384 + t];
    __syncthreads();

    const float* __restrict__ xr = g_xn + b * 32768;
    const float* __restrict__ yr = g_yn + b * 32768;

    float A = 0.f, B = 0.f;
#pragma unroll 4
    for (int c = 0; c < 128; c++) {
        const float xv = xr[c * 256 + j];
        const float yv = yr[c * 256 + j];
        A = fmaf(ws[c],       xv, A);
        B = fmaf(ws[128 + c], xv, B);
        B = fmaf(ws[256 + c], yv, B);
    }

    float sA = warp_sum(A), sA2 = warp_sum(A * A);
    float sB = warp_sum(B), sB2 = warp_sum(B * B);
    const int lane = j & 31, wid = j >> 5;
    if (lane == 0) {
        red[wid] = sA; red[8 + wid] = sA2; red[16 + wid] = sB; red[24 + wid] = sB2;
    }
    __syncthreads();
    float tA = 0.f, tA2 = 0.f, tB = 0.f, tB2 = 0.f;
#pragma unroll
    for (int w = 0; w < 8; w++) {
        tA += red[w]; tA2 += red[8 + w]; tB += red[16 + w]; tB2 += red[24 + w];
    }
    const float mA = tA * (1.f / 256.f);
    const float mB = tB * (1.f / 256.f);
    const float vA = tA2 * (1.f / 256.f) - mA * mA;
    const float vB = tB2 * (1.f / 256.f) - mB * mB;
    const float rs = rsqrtf(vA + vB + EPSF);

    const float ap = (A - mA) * rs;   // a'_j
    const float bp = (B - mB) * rs;   // b'_i  (thread index doubles as i)
    as[j] = ap;
    __syncthreads();

    float acc = 0.f;
#pragma unroll 8
    for (int jj = 0; jj < 256; jj++)
        acc += fmaxf(as[jj] + bp, 0.f);

    g_s[bid * 256 + j] = acc;
}

// ---------------------------------------------------------------------------
// Kernel 3: out[b,p,i] = sum_o w2[p,o] * s[b,o,i] + 256*b2[p]
// grid = 256 blocks (b*128+p), 256 threads (i).
// ---------------------------------------------------------------------------
__global__ void k_out(const float* __restrict__ w2, const float* __restrict__ b2,
                      float* __restrict__ out) {
    __shared__ float ws[128];
    const int bid = blockIdx.x;
    const int b   = bid >> 7;
    const int p   = bid & 127;
    const int i   = threadIdx.x;

    if (i < 128) ws[i] = w2[p * 128 + i];
    __syncthreads();

    const float* __restrict__ sr = g_s + b * 32768;
    float acc = 256.f * b2[p];
#pragma unroll 4
    for (int o = 0; o < 128; o++)
        acc = fmaf(ws[o], sr[o * 256 + i], acc);

    out[bid * 256 + i] = acc;
}

extern "C" void kernel_launch(void* const* d_in, const int* in_sizes, int n_in,
                              void* d_out, int out_size) {
    const float* x   = (const float*)d_in[0];   // (2,128,16,16)
    const float* y   = (const float*)d_in[1];   // (2,128,16,16)
    const float* pos = (const float*)d_in[2];   // (256,128)
    const float* w1  = (const float*)d_in[3];   // (128,384)
    // d_in[4] = b1 — provably unused (cancels in centering)
    const float* w2  = (const float*)d_in[5];   // (128,128)
    const float* b2  = (const float*)d_in[6];   // (128,)
    float* out = (float*)d_out;                 // (2,128,16,16)

    k_norm<<<512, 256>>>(x, y, pos);
    k_relate<<<256, 256>>>(w1);
    k_out<<<256, 256>>>(w2, b2, out);
}

// round 3
// speedup vs baseline: 1.3876x; 1.3876x over previous
#include <cuda_runtime.h>

#define EPSF 1e-5f
#define NB   128          // 128 blocks < 148 SMs -> all co-resident, grid barrier is safe

// Scratch (__device__ globals per allocation-free rule)
__device__ float2 g_xy[2 * 128 * 256];   // interleaved {xn, yn}, (b, c, hw)
__device__ float  g_s [2 * 128 * 256];   // s[b, o, i]
__device__ unsigned g_bar = 0;
__device__ volatile unsigned g_gen = 0;

// Software grid barrier. Safe because all NB blocks are resident in wave 1.
// Generation-based: reusable across barriers and across graph replays.
__device__ __forceinline__ void grid_barrier() {
    __syncthreads();
    if (threadIdx.x == 0) {
        __threadfence();                       // publish this block's global writes
        unsigned gen = g_gen;
        if (atomicAdd(&g_bar, 1u) == NB - 1) {
            g_bar = 0;
            __threadfence();
            g_gen = gen + 1;                   // release
        } else {
            while (g_gen == gen) { }           // spin (1 thread/block)
        }
    }
    __syncthreads();
}

// Block-wide reduction of 4 values. Internal syncs make back-to-back calls safe.
__device__ __forceinline__ void red4(float a, float b, float c, float d,
                                     float* red, float out[4], int lane, int wid) {
#pragma unroll
    for (int o = 16; o > 0; o >>= 1) {
        a += __shfl_down_sync(0xffffffffu, a, o);
        b += __shfl_down_sync(0xffffffffu, b, o);
        c += __shfl_down_sync(0xffffffffu, c, o);
        d += __shfl_down_sync(0xffffffffu, d, o);
    }
    __syncthreads();
    if (lane == 0) { red[wid] = a; red[8 + wid] = b; red[16 + wid] = c; red[24 + wid] = d; }
    __syncthreads();
    float t0 = 0.f, t1 = 0.f, t2 = 0.f, t3 = 0.f;
#pragma unroll
    for (int w = 0; w < 8; w++) {
        t0 += red[w]; t1 += red[8 + w]; t2 += red[16 + w]; t3 += red[24 + w];
    }
    out[0] = t0; out[1] = t1; out[2] = t2; out[3] = t3;
}

// ---------------------------------------------------------------------------
// One persistent kernel, 128 blocks x 256 threads:
//  preload: w1 rows (2), w2 rows (2), b2 pair into smem (overlaps phase 1)
//  phase 1: two (x,y) row-pairs per block: pos add + instance norm + relu,
//           write interleaved float2 -> g_xy
//  phase 2: block (b, o0..o0+1): fused GEMVs A/B, separable inorm of z
//           (b1 cancels; var = varA+varB, cross term exactly 0), relu-sum -> g_s
//  phase 3: block (b, p0..p0+1): out = w2 @ s + 256*b2
// ---------------------------------------------------------------------------
__global__ void __launch_bounds__(256, 1)
rn_fused(const float* __restrict__ x, const float* __restrict__ y,
         const float* __restrict__ pos, const float* __restrict__ w1,
         const float* __restrict__ w2, const float* __restrict__ b2,
         float* __restrict__ out) {
    __shared__ __align__(16) float s_w1[768];
    __shared__ __align__(16) float s_w2[256];
    __shared__ __align__(16) float s_as[512];   // float4-read below: MUST be 16B aligned
    __shared__ __align__(16) float s_red[32];
    __shared__ float s_b2[2];

    const int i    = threadIdx.x;
    const int lane = i & 31, wid = i >> 5;
    const int bid  = blockIdx.x;
    const int b    = bid >> 6;            // batch for phases 2/3
    const int o0   = (bid & 63) * 2;      // channel pair for phases 2/3

    // ---- preload weights (first use is after grid_barrier -> no sync needed) ----
    {
        const float* w1r = w1 + o0 * 384;
#pragma unroll
        for (int t = i; t < 768; t += 256) s_w1[t] = w1r[t];
        s_w2[i] = w2[o0 * 128 + i];
        if (i < 2) s_b2[i] = b2[o0 + i];
    }

    // ---- phase 1: norm+relu of two x rows and two y rows ----
    {
        const int idx0 = bid * 2;                 // row index pair (same batch)
        const int c0   = idx0 & 127;              // even
        const float2 pv = ((const float2*)pos)[i * 64 + (c0 >> 1)];
#pragma unroll
        for (int k = 0; k < 2; k++) {
            const int idx = idx0 + k;
            float xv = x[idx * 256 + i] + (k ? pv.y : pv.x);
            float yv = y[idx * 256 + i];
            float r[4];
            red4(xv, xv * xv, yv, yv * yv, s_red, r, lane, wid);
            const float inv = 1.f / 256.f;
            const float mx = r[0] * inv, my = r[2] * inv;
            const float rx = rsqrtf(r[1] * inv - mx * mx + EPSF);
            const float ry = rsqrtf(r[3] * inv - my * my + EPSF);
            g_xy[idx * 256 + i] = make_float2(fmaxf((xv - mx) * rx, 0.f),
                                              fmaxf((yv - my) * ry, 0.f));
        }
    }

    grid_barrier();

    // ---- phase 2: relate for (b, o0) and (b, o0+1) ----
    {
        const float2* __restrict__ xy = g_xy + b * 32768;
        float A0 = 0.f, B0 = 0.f, A1 = 0.f, B1 = 0.f;
#pragma unroll 8
        for (int c = 0; c < 128; c++) {
            const float2 v = __ldcg(&xy[c * 256 + i]);
            A0 = fmaf(s_w1[c],       v.x, A0);
            B0 = fmaf(s_w1[128 + c], v.x, B0);
            B0 = fmaf(s_w1[256 + c], v.y, B0);
            A1 = fmaf(s_w1[384 + c], v.x, A1);
            B1 = fmaf(s_w1[512 + c], v.x, B1);
            B1 = fmaf(s_w1[640 + c], v.y, B1);
        }
        float r0[4], r1[4];
        red4(A0, A0 * A0, B0, B0 * B0, s_red, r0, lane, wid);
        red4(A1, A1 * A1, B1, B1 * B1, s_red, r1, lane, wid);
        const float inv = 1.f / 256.f;
        const float mA0 = r0[0] * inv, mB0 = r0[2] * inv;
        const float mA1 = r1[0] * inv, mB1 = r1[2] * inv;
        const float rs0 = rsqrtf((r0[1] * inv - mA0 * mA0) + (r0[3] * inv - mB0 * mB0) + EPSF);
        const float rs1 = rsqrtf((r1[1] * inv - mA1 * mA1) + (r1[3] * inv - mB1 * mB1) + EPSF);
        s_as[i]       = (A0 - mA0) * rs0;
        s_as[256 + i] = (A1 - mA1) * rs1;
        const float bp0 = (B0 - mB0) * rs0;
        const float bp1 = (B1 - mB1) * rs1;
        __syncthreads();

        float acc0 = 0.f, acc1 = 0.f;
        const float4* a4 = (const float4*)s_as;
#pragma unroll 8
        for (int q = 0; q < 64; q++) {
            const float4 u = a4[q];
            acc0 += fmaxf(u.x + bp0, 0.f) + fmaxf(u.y + bp0, 0.f)
                  + fmaxf(u.z + bp0, 0.f) + fmaxf(u.w + bp0, 0.f);
            const float4 v = a4[64 + q];
            acc1 += fmaxf(v.x + bp1, 0.f) + fmaxf(v.y + bp1, 0.f)
                  + fmaxf(v.z + bp1, 0.f) + fmaxf(v.w + bp1, 0.f);
        }
        g_s[(b * 128 + o0)     * 256 + i] = acc0;
        g_s[(b * 128 + o0 + 1) * 256 + i] = acc1;
    }

    grid_barrier();

    // ---- phase 3: out[b,p,:] for p = o0, o0+1 ----
    {
        const float* __restrict__ sr = g_s + b * 32768;
        float acc0 = 256.f * s_b2[0];
        float acc1 = 256.f * s_b2[1];
#pragma unroll 8
        for (int o = 0; o < 128; o++) {
            const float sv = __ldcg(&sr[o * 256 + i]);
            acc0 = fmaf(s_w2[o],       sv, acc0);
            acc1 = fmaf(s_w2[128 + o], sv, acc1);
        }
        out[(b * 128 + o0)     * 256 + i] = acc0;
        out[(b * 128 + o0 + 1) * 256 + i] = acc1;
    }
}

extern "C" void kernel_launch(void* const* d_in, const int* in_sizes, int n_in,
                              void* d_out, int out_size) {
    const float* x   = (const float*)d_in[0];   // (2,128,16,16)
    const float* y   = (const float*)d_in[1];   // (2,128,16,16)
    const float* pos = (const float*)d_in[2];   // (256,128)
    const float* w1  = (const float*)d_in[3];   // (128,384)
    // d_in[4] = b1 — provably unused (cancels in instance-norm centering)
    const float* w2  = (const float*)d_in[5];   // (128,128)
    const float* b2  = (const float*)d_in[6];   // (128,)
    float* out = (float*)d_out;                 // (2,128,16,16)

    rn_fused<<<NB, 256>>>(x, y, pos, w1, w2, b2, out);
}

// round 4
// speedup vs baseline: 1.5359x; 1.1068x over previous
#include <cuda_runtime.h>

#define EPSF 1e-5f
#define NB   128          // 128 blocks < 148 SMs -> all co-resident, grid barrier is safe

// Scratch (__device__ globals per allocation-free rule)
__device__ float2 g_xy[2 * 128 * 256];   // interleaved {xn, yn}, (b, c, hw)
__device__ float  g_s [2 * 128 * 256];   // s[b, o, i]
__device__ unsigned g_bar = 0;
__device__ volatile unsigned g_gen = 0;

// Software grid barrier (all NB blocks resident in wave 1; generation-based,
// reusable across barriers and graph replays).
__device__ __forceinline__ void grid_barrier() {
    __syncthreads();
    if (threadIdx.x == 0) {
        __threadfence();
        unsigned gen = g_gen;
        if (atomicAdd(&g_bar, 1u) == NB - 1) {
            g_bar = 0;
            __threadfence();
            g_gen = gen + 1;
        } else {
            while (g_gen == gen) { }
        }
    }
    __syncthreads();
}

// Group-wide (256-thread) reduction of 4 values; two groups (ch=0/1) reduce
// concurrently in disjoint smem slices. All 512 threads must reach the syncs.
__device__ __forceinline__ void red4g(float a, float b, float c, float d,
                                      float* red /*[64]*/, float out[4],
                                      int lane, int gwid /*0..7*/, int ch) {
#pragma unroll
    for (int o = 16; o > 0; o >>= 1) {
        a += __shfl_down_sync(0xffffffffu, a, o);
        b += __shfl_down_sync(0xffffffffu, b, o);
        c += __shfl_down_sync(0xffffffffu, c, o);
        d += __shfl_down_sync(0xffffffffu, d, o);
    }
    __syncthreads();
    if (lane == 0) {
        float* r = red + ch * 32;
        r[gwid] = a; r[8 + gwid] = b; r[16 + gwid] = c; r[24 + gwid] = d;
    }
    __syncthreads();
    const float* r = red + ch * 32;
    float t0 = 0.f, t1 = 0.f, t2 = 0.f, t3 = 0.f;
#pragma unroll
    for (int w = 0; w < 8; w++) {
        t0 += r[w]; t1 += r[8 + w]; t2 += r[16 + w]; t3 += r[24 + w];
    }
    out[0] = t0; out[1] = t1; out[2] = t2; out[3] = t3;
}

// ---------------------------------------------------------------------------
// One persistent kernel, 128 blocks x 512 threads (16 warps/SM):
//  phase 1: group g normalizes row idx=bid*2+g of x (+pos) and y -> g_xy
//  phase 2: groups split the c-GEMV loop in halves (combine in smem), then
//           remap to channels for separable inorm + relu-sum -> g_s
//  phase 3: groups split the o-loop in halves, combine -> out
// Total L2 traffic identical to the 256-thread version; latency exposure/thread halved.
// ---------------------------------------------------------------------------
__global__ void __launch_bounds__(512, 1)
rn_fused(const float* __restrict__ x, const float* __restrict__ y,
         const float* __restrict__ pos, const float* __restrict__ w1,
         const float* __restrict__ w2, const float* __restrict__ b2,
         float* __restrict__ out) {
    __shared__ __align__(16) float s_w1[768];
    __shared__ __align__(16) float s_w2[256];
    __shared__ __align__(16) float s_as[512];     // a' per channel (float4-read)
    __shared__ __align__(16) float s_pa[2][512];  // partials (A per channel / phase-3)
    __shared__ __align__(16) float s_pb[2][512];  // partials (B per channel)
    __shared__ __align__(16) float s_red[64];
    __shared__ float s_b2[2];

    const int i    = threadIdx.x;          // 0..511
    const int g    = i >> 8;               // group 0/1
    const int j    = i & 255;              // lane within group
    const int lane = i & 31;
    const int gwid = (i >> 5) & 7;         // warp id within group
    const int bid  = blockIdx.x;
    const int b    = bid >> 6;             // batch for phases 2/3
    const int o0   = (bid & 63) * 2;       // channel pair for phases 2/3

    // ---- preload weights (first use after grid_barrier) ----
    for (int t = i; t < 768; t += 512) s_w1[t] = w1[o0 * 384 + t];
    if (i < 256) s_w2[i] = w2[o0 * 128 + i];
    if (i < 2)   s_b2[i] = b2[o0 + i];

    // ---- phase 1: group g handles row idx (x with pos, and y) ----
    {
        const int idx = bid * 2 + g;
        const int c   = idx & 127;
        float xv = x[idx * 256 + j] + pos[j * 128 + c];
        float yv = y[idx * 256 + j];
        float r[4];
        red4g(xv, xv * xv, yv, yv * yv, s_red, r, lane, gwid, g);
        const float inv = 1.f / 256.f;
        const float mx = r[0] * inv, my = r[2] * inv;
        const float rx = rsqrtf(r[1] * inv - mx * mx + EPSF);
        const float ry = rsqrtf(r[3] * inv - my * my + EPSF);
        g_xy[idx * 256 + j] = make_float2(fmaxf((xv - mx) * rx, 0.f),
                                          fmaxf((yv - my) * ry, 0.f));
    }

    grid_barrier();

    // ---- phase 2: relate for (b, o0) and (b, o0+1) ----
    {
        const float2* __restrict__ xy = g_xy + b * 32768;
        float A0 = 0.f, B0 = 0.f, A1 = 0.f, B1 = 0.f;
        const int cbase = g * 64;
#pragma unroll 8
        for (int cc = 0; cc < 64; cc++) {
            const int c = cbase + cc;
            const float2 v = __ldcg(&xy[c * 256 + j]);
            A0 = fmaf(s_w1[c],       v.x, A0);
            B0 = fmaf(s_w1[128 + c], v.x, B0);
            B0 = fmaf(s_w1[256 + c], v.y, B0);
            A1 = fmaf(s_w1[384 + c], v.x, A1);
            B1 = fmaf(s_w1[512 + c], v.x, B1);
            B1 = fmaf(s_w1[640 + c], v.y, B1);
        }
        s_pa[0][i] = A0; s_pa[1][i] = A1;
        s_pb[0][i] = B0; s_pb[1][i] = B1;
        __syncthreads();

        // remap: group index now selects the output channel ch = g
        const float A = s_pa[g][j] + s_pa[g][256 + j];
        const float B = s_pb[g][j] + s_pb[g][256 + j];

        float r[4];
        red4g(A, A * A, B, B * B, s_red, r, lane, gwid, g);
        const float inv = 1.f / 256.f;
        const float mA = r[0] * inv, mB = r[2] * inv;
        const float rs = rsqrtf((r[1] * inv - mA * mA) + (r[3] * inv - mB * mB) + EPSF);
        s_as[g * 256 + j] = (A - mA) * rs;
        const float bp  = (B - mB) * rs;
        __syncthreads();

        float acc = 0.f;
        const float4* a4 = (const float4*)(s_as + g * 256);
#pragma unroll 8
        for (int q = 0; q < 64; q++) {
            const float4 u = a4[q];
            acc += fmaxf(u.x + bp, 0.f) + fmaxf(u.y + bp, 0.f)
                 + fmaxf(u.z + bp, 0.f) + fmaxf(u.w + bp, 0.f);
        }
        g_s[(b * 128 + o0 + g) * 256 + j] = acc;
    }

    grid_barrier();

    // ---- phase 3: out[b, o0+ch, :] ; groups split the o-loop ----
    {
        const float* __restrict__ sr = g_s + b * 32768;
        float a0 = 0.f, a1 = 0.f;
        const int obase = g * 64;
#pragma unroll 8
        for (int oo = 0; oo < 64; oo++) {
            const int o = obase + oo;
            const float sv = __ldcg(&sr[o * 256 + j]);
            a0 = fmaf(s_w2[o],       sv, a0);
            a1 = fmaf(s_w2[128 + o], sv, a1);
        }
        s_pa[0][i] = a0; s_pa[1][i] = a1;
        __syncthreads();

        const float r = s_pa[g][j] + s_pa[g][256 + j] + 256.f * s_b2[g];
        out[(b * 128 + o0 + g) * 256 + j] = r;
    }
}

extern "C" void kernel_launch(void* const* d_in, const int* in_sizes, int n_in,
                              void* d_out, int out_size) {
    const float* x   = (const float*)d_in[0];   // (2,128,16,16)
    const float* y   = (const float*)d_in[1];   // (2,128,16,16)
    const float* pos = (const float*)d_in[2];   // (256,128)
    const float* w1  = (const float*)d_in[3];   // (128,384)
    // d_in[4] = b1 — provably unused (cancels in instance-norm centering)
    const float* w2  = (const float*)d_in[5];   // (128,128)
    const float* b2  = (const float*)d_in[6];   // (128,)
    float* out = (float*)d_out;                 // (2,128,16,16)

    rn_fused<<<NB, 512>>>(x, y, pos, w1, w2, b2, out);
}

// round 5
// speedup vs baseline: 1.6912x; 1.1011x over previous
#include <cuda_runtime.h>

#define EPSF 1e-5f
#define NB   128   // 128 blocks < 148 SMs -> all co-resident; per-batch barriers over 64 blocks

// Scratch (__device__ globals per allocation-free rule)
__device__ float2 g_xy[2 * 128 * 256];     // interleaved {xn, yn}, (b, c, hw)
__device__ float  g_s [2 * 128 * 256];     // s[b, o, i]
__device__ unsigned g_bar2[2] = {0, 0};
__device__ volatile unsigned g_gen2[2] = {0, 0};

// ---- packed f32x2 helpers ----
__device__ __forceinline__ unsigned long long pk2(float a, float b) {
    unsigned long long r;
    asm("mov.b64 %0, {%1, %2};" : "=l"(r) : "f"(a), "f"(b));
    return r;
}
__device__ __forceinline__ unsigned long long dup2(float a) {
    unsigned long long r;
    asm("mov.b64 %0, {%1, %1};" : "=l"(r) : "f"(a));
    return r;
}
__device__ __forceinline__ float2 upk2(unsigned long long v) {
    float a, b;
    asm("mov.b64 {%0, %1}, %2;" : "=f"(a), "=f"(b) : "l"(v));
    return make_float2(a, b);
}
__device__ __forceinline__ unsigned long long fma2(unsigned long long a,
                                                   unsigned long long b,
                                                   unsigned long long c) {
    unsigned long long r;
    asm("fma.rn.f32x2 %0, %1, %2, %3;" : "=l"(r) : "l"(a), "l"(b), "l"(c));
    return r;
}
__device__ __forceinline__ unsigned long long add2(unsigned long long a,
                                                   unsigned long long b) {
    unsigned long long r;
    asm("add.rn.f32x2 %0, %1, %2;" : "=l"(r) : "l"(a), "l"(b));
    return r;
}

// Per-batch grid barrier over 64 blocks (generation-based; reusable across
// barriers and graph replays).
__device__ __forceinline__ void batch_barrier(int bb) {
    __syncthreads();
    if (threadIdx.x == 0) {
        __threadfence();
        unsigned gen = g_gen2[bb];
        if (atomicAdd(&g_bar2[bb], 1u) == 63u) {
            g_bar2[bb] = 0;
            __threadfence();
            g_gen2[bb] = gen + 1;
        } else {
            while (g_gen2[bb] == gen) { }
        }
    }
    __syncthreads();
}

// Group-wide (256-thread) reduction of 4 values; two groups reduce concurrently
// in disjoint smem slices. All 512 threads must reach the syncs.
__device__ __forceinline__ void red4g(float a, float b, float c, float d,
                                      float* red /*[64]*/, float out[4],
                                      int lane, int gwid, int ch) {
#pragma unroll
    for (int o = 16; o > 0; o >>= 1) {
        a += __shfl_down_sync(0xffffffffu, a, o);
        b += __shfl_down_sync(0xffffffffu, b, o);
        c += __shfl_down_sync(0xffffffffu, c, o);
        d += __shfl_down_sync(0xffffffffu, d, o);
    }
    __syncthreads();
    if (lane == 0) {
        float* r = red + ch * 32;
        r[gwid] = a; r[8 + gwid] = b; r[16 + gwid] = c; r[24 + gwid] = d;
    }
    __syncthreads();
    const float* r = red + ch * 32;
    float t0 = 0.f, t1 = 0.f, t2 = 0.f, t3 = 0.f;
#pragma unroll
    for (int w = 0; w < 8; w++) {
        t0 += r[w]; t1 += r[8 + w]; t2 += r[16 + w]; t3 += r[24 + w];
    }
    out[0] = t0; out[1] = t1; out[2] = t2; out[3] = t3;
}

// ---------------------------------------------------------------------------
// One persistent kernel, 128 blocks x 512 threads.
//  phase 1: group g normalizes row bid*2+g of x (+pos) and y -> g_xy
//  phase 2: groups split c-GEMV (packed f32x2 over the channel pair), combine,
//           separable inorm; relu-sum via  s[i] = 128 b'_i + 0.5 * sum_j|a'_j+b'_i|
//           (valid because sum_j a'_j = 0 after centering)
//  phase 3: groups split o-loop (packed f32x2 over output-channel pair)
// Barriers are per-batch (64 blocks), since all deps are batch-local.
// ---------------------------------------------------------------------------
__global__ void __launch_bounds__(512, 1)
rn_fused(const float* __restrict__ x, const float* __restrict__ y,
         const float* __restrict__ pos, const float* __restrict__ w1,
         const float* __restrict__ w2, const float* __restrict__ b2,
         float* __restrict__ out) {
    __shared__ __align__(16) float2 s_wA[128];    // {Wi_o0[c], Wi_o1[c]}
    __shared__ __align__(16) float2 s_wB[128];    // {Wj_o0[c], Wj_o1[c]}
    __shared__ __align__(16) float2 s_wY[128];    // {Wy_o0[c], Wy_o1[c]}
    __shared__ __align__(16) float2 s_w2p[128];   // {w2_p0[o], w2_p1[o]}
    __shared__ __align__(16) float  s_as[512];    // a' per channel (float4-read)
    __shared__ __align__(16) float2 s_pa[512];    // packed partial exchange
    __shared__ __align__(16) float2 s_pb[512];
    __shared__ __align__(16) float  s_red[64];
    __shared__ float s_b2[2];

    const int i    = threadIdx.x;          // 0..511
    const int g    = i >> 8;               // group 0/1
    const int j    = i & 255;              // lane within group
    const int lane = i & 31;
    const int gwid = (i >> 5) & 7;
    const int bid  = blockIdx.x;
    const int bb   = bid >> 6;             // batch (for barriers AND phases 2/3)
    const int o0   = (bid & 63) * 2;       // channel pair

    // ---- preload packed weights (first use after batch_barrier) ----
    if (i < 128) {
        const float* w1r = w1 + o0 * 384;
        s_wA[i]  = make_float2(w1r[i],       w1r[384 + i]);
        s_wB[i]  = make_float2(w1r[128 + i], w1r[512 + i]);
        s_wY[i]  = make_float2(w1r[256 + i], w1r[640 + i]);
        const float* w2r = w2 + o0 * 128;
        s_w2p[i] = make_float2(w2r[i], w2r[128 + i]);
    }
    if (i < 2) s_b2[i] = b2[o0 + i];

    // ---- phase 1: group g normalizes row idx = bid*2+g (x with pos, and y) ----
    {
        const int idx = bid * 2 + g;
        const int c   = idx & 127;
        float xv = x[idx * 256 + j] + pos[j * 128 + c];
        float yv = y[idx * 256 + j];
        float r[4];
        red4g(xv, xv * xv, yv, yv * yv, s_red, r, lane, gwid, g);
        const float inv = 1.f / 256.f;
        const float mx = r[0] * inv, my = r[2] * inv;
        const float rx = rsqrtf(r[1] * inv - mx * mx + EPSF);
        const float ry = rsqrtf(r[3] * inv - my * my + EPSF);
        g_xy[idx * 256 + j] = make_float2(fmaxf((xv - mx) * rx, 0.f),
                                          fmaxf((yv - my) * ry, 0.f));
    }

    batch_barrier(bb);

    // ---- phase 2: relate for (bb, o0) and (bb, o0+1), packed over the pair ----
    {
        const float2* __restrict__ xy = g_xy + bb * 32768;
        unsigned long long accA = 0ull, accB = 0ull;   // packed (ch0, ch1)
        const int cbase = g * 64;
#pragma unroll 8
        for (int cc = 0; cc < 64; cc++) {
            const int c = cbase + cc;
            const float2 v = __ldcg(&xy[c * 256 + j]);
            const unsigned long long xx = dup2(v.x);
            const unsigned long long yy = dup2(v.y);
            accA = fma2(*(const unsigned long long*)&s_wA[c], xx, accA);
            accB = fma2(*(const unsigned long long*)&s_wB[c], xx, accB);
            accB = fma2(*(const unsigned long long*)&s_wY[c], yy, accB);
        }
        s_pa[i] = upk2(accA);
        s_pb[i] = upk2(accB);
        __syncthreads();

        // combine group partials; group index now selects output channel g
        float A, B;
        if (g == 0) { A = s_pa[j].x + s_pa[256 + j].x; B = s_pb[j].x + s_pb[256 + j].x; }
        else        { A = s_pa[j].y + s_pa[256 + j].y; B = s_pb[j].y + s_pb[256 + j].y; }

        float r[4];
        red4g(A, A * A, B, B * B, s_red, r, lane, gwid, g);
        const float inv = 1.f / 256.f;
        const float mA = r[0] * inv, mB = r[2] * inv;
        const float rs = rsqrtf((r[1] * inv - mA * mA) + (r[3] * inv - mB * mB) + EPSF);
        s_as[g * 256 + j] = (A - mA) * rs;
        const float bp  = (B - mB) * rs;
        __syncthreads();

        // s[i] = 128*bp + 0.5 * sum_j |a'_j + bp|   (sum_j a'_j = 0)
        const unsigned long long bp2 = dup2(bp);
        float sabs = 0.f;
        const float4* a4 = (const float4*)(s_as + g * 256);
#pragma unroll 8
        for (int q = 0; q < 64; q++) {
            const float4 u = a4[q];
            const float2 t0 = upk2(add2(pk2(u.x, u.y), bp2));
            const float2 t1 = upk2(add2(pk2(u.z, u.w), bp2));
            sabs += fabsf(t0.x); sabs += fabsf(t0.y);
            sabs += fabsf(t1.x); sabs += fabsf(t1.y);
        }
        g_s[(bb * 128 + o0 + g) * 256 + j] = fmaf(128.f, bp, 0.5f * sabs);
    }

    batch_barrier(bb);

    // ---- phase 3: out[bb, o0+ch, :]; groups split the o-loop, packed over pair ----
    {
        const float* __restrict__ sr = g_s + bb * 32768;
        unsigned long long acc = 0ull;                 // packed (p0, p1)
        const int obase = g * 64;
#pragma unroll 8
        for (int oo = 0; oo < 64; oo++) {
            const int o = obase + oo;
            const float sv = __ldcg(&sr[o * 256 + j]);
            acc = fma2(*(const unsigned long long*)&s_w2p[o], dup2(sv), acc);
        }
        s_pa[i] = upk2(acc);
        __syncthreads();

        const float part = (g == 0) ? (s_pa[j].x + s_pa[256 + j].x)
                                    : (s_pa[j].y + s_pa[256 + j].y);
        out[(bb * 128 + o0 + g) * 256 + j] = part + 256.f * s_b2[g];
    }
}

extern "C" void kernel_launch(void* const* d_in, const int* in_sizes, int n_in,
                              void* d_out, int out_size) {
    const float* x   = (const float*)d_in[0];   // (2,128,16,16)
    const float* y   = (const float*)d_in[1];   // (2,128,16,16)
    const float* pos = (const float*)d_in[2];   // (256,128)
    const float* w1  = (const float*)d_in[3];   // (128,384)
    // d_in[4] = b1 — provably unused (cancels in instance-norm centering)
    const float* w2  = (const float*)d_in[5];   // (128,128)
    const float* b2  = (const float*)d_in[6];   // (128,)
    float* out = (float*)d_out;                 // (2,128,16,16)

    rn_fused<<<NB, 512>>>(x, y, pos, w1, w2, b2, out);
}